// round 15
// baseline (speedup 1.0000x reference)
#include <cuda_runtime.h>
#include <math.h>

#define BB    8
#define CIN   64
#define CR    32
#define HH    128
#define WW    128
#define NN    16384
#define COUT  64
#define CNT   (BB * NN)

// ---------------- device scratch ----------------
__device__ float g_xr[(size_t)BB * CR * NN];         // reduced features [b][cr][N]  16 MB
__device__ float g_att[(size_t)BB * 8 * NN];         // [b][rq][N]: rq 0-3 a_src, 4-7 a_dst
__device__ float g_pre[(size_t)BB * COUT * NN];      // pre-BN 33.5 MB
__device__ float g_sum[COUT];
__device__ float g_sumsq[COUT];

// ---------------- kernel 1: xr = w_reduce @ x + attention rows + q inline ---
// 256 nodes / block, 256 threads, DYNAMIC smem (75776 B). (measured ~39us)
#define X_XS    0                      // [64][256] x tile; reused as xr [32][260]
#define X_WR    16384                  // [64][36] w_reduce^T
#define X_QS    18688                  // [32][8]  q^T
#define X_TOT   18944                  // floats -> 75776 bytes

__global__ __launch_bounds__(256) void k_xr(
    const float* __restrict__ x,
    const float* __restrict__ w_reduce,
    const float* __restrict__ w_lin,
    const float* __restrict__ att_src,
    const float* __restrict__ att_dst)
{
    extern __shared__ float SX[];
    float* xs   = SX + X_XS;
    float* wr_s = SX + X_WR;
    float* qs   = SX + X_QS;

    const int t = threadIdx.x;
    const int b = blockIdx.x >> 6;
    const int nodeBase = (blockIdx.x & 63) << 8;

    if (blockIdx.x == 0 && t < COUT) { g_sum[t] = 0.f; g_sumsq[t] = 0.f; }

    {
        const float4* xg = (const float4*)x;
        float4* xs4 = (float4*)xs;
        #pragma unroll
        for (int i = 0; i < 16; i++) {
            int idx = t + i * 256;
            int c = idx >> 6, nq = idx & 63;
            xs4[idx] = xg[((size_t)(b * CIN + c)) * (NN / 4) + (nodeBase >> 2) + nq];
        }
    }
    #pragma unroll
    for (int i = 0; i < 8; i++) {
        int idx = t + i * 256;
        int cr = idx >> 6, c = idx & 63;
        wr_s[c * 36 + cr] = w_reduce[idx];
    }
    {
        int rq = t >> 5, k = t & 31, h = rq & 3;
        const float* av = (rq < 4) ? att_src : att_dst;
        float acc = 0.f;
        #pragma unroll
        for (int c = 0; c < CR; c++)
            acc += av[h * CR + c] * w_lin[(h * CR + c) * CR + k];
        qs[k * 8 + rq] = acc;
    }
    __syncthreads();

    const int crq = t & 7;
    const int cr0 = crq << 2;
    const int n0  = (t >> 3) << 3;
    float a1[4][8];
    #pragma unroll
    for (int i = 0; i < 4; i++)
        #pragma unroll
        for (int j = 0; j < 8; j++) a1[i][j] = 0.f;

    #pragma unroll
    for (int c = 0; c < CIN; c++) {
        float4 wv = *(const float4*)&wr_s[c * 36 + cr0];
        float4 xa = *(const float4*)&xs[c * 256 + n0];
        float4 xb = *(const float4*)&xs[c * 256 + n0 + 4];
        a1[0][0] += wv.x * xa.x; a1[0][1] += wv.x * xa.y; a1[0][2] += wv.x * xa.z; a1[0][3] += wv.x * xa.w;
        a1[0][4] += wv.x * xb.x; a1[0][5] += wv.x * xb.y; a1[0][6] += wv.x * xb.z; a1[0][7] += wv.x * xb.w;
        a1[1][0] += wv.y * xa.x; a1[1][1] += wv.y * xa.y; a1[1][2] += wv.y * xa.z; a1[1][3] += wv.y * xa.w;
        a1[1][4] += wv.y * xb.x; a1[1][5] += wv.y * xb.y; a1[1][6] += wv.y * xb.z; a1[1][7] += wv.y * xb.w;
        a1[2][0] += wv.z * xa.x; a1[2][1] += wv.z * xa.y; a1[2][2] += wv.z * xa.z; a1[2][3] += wv.z * xa.w;
        a1[2][4] += wv.z * xb.x; a1[2][5] += wv.z * xb.y; a1[2][6] += wv.z * xb.z; a1[2][7] += wv.z * xb.w;
        a1[3][0] += wv.w * xa.x; a1[3][1] += wv.w * xa.y; a1[3][2] += wv.w * xa.z; a1[3][3] += wv.w * xa.w;
        a1[3][4] += wv.w * xb.x; a1[3][5] += wv.w * xb.y; a1[3][6] += wv.w * xb.z; a1[3][7] += wv.w * xb.w;
    }

    #pragma unroll
    for (int i = 0; i < 4; i++) {
        float4 va = make_float4(a1[i][0], a1[i][1], a1[i][2], a1[i][3]);
        float4 vb = make_float4(a1[i][4], a1[i][5], a1[i][6], a1[i][7]);
        size_t base = ((size_t)(b * CR + cr0 + i)) * NN + nodeBase + n0;
        *(float4*)&g_xr[base]     = va;
        *(float4*)&g_xr[base + 4] = vb;
    }
    __syncthreads();
    float* xrs = xs;     // [32][260]
    #pragma unroll
    for (int i = 0; i < 4; i++) {
        float4 va = make_float4(a1[i][0], a1[i][1], a1[i][2], a1[i][3]);
        float4 vb = make_float4(a1[i][4], a1[i][5], a1[i][6], a1[i][7]);
        *(float4*)&xrs[(cr0 + i) * 260 + n0]     = va;
        *(float4*)&xrs[(cr0 + i) * 260 + n0 + 4] = vb;
    }
    __syncthreads();

    const int rq   = t >> 5;
    const int lane = t & 31;
    const int na   = lane << 3;
    float p[8];
    #pragma unroll
    for (int i = 0; i < 8; i++) p[i] = 0.f;
    #pragma unroll
    for (int k = 0; k < CR; k++) {
        float qv = qs[k * 8 + rq];
        float4 xa = *(const float4*)&xrs[k * 260 + na];
        float4 xb = *(const float4*)&xrs[k * 260 + na + 4];
        p[0] += qv * xa.x; p[1] += qv * xa.y; p[2] += qv * xa.z; p[3] += qv * xa.w;
        p[4] += qv * xb.x; p[5] += qv * xb.y; p[6] += qv * xb.z; p[7] += qv * xb.w;
    }
    {
        size_t base = ((size_t)(b * 8 + rq)) * NN + nodeBase + na;
        *(float4*)&g_att[base]     = make_float4(p[0], p[1], p[2], p[3]);
        *(float4*)&g_att[base + 4] = make_float4(p[4], p[5], p[6], p[7]);
    }
}

// ---------------- kernel 2: fused agg + per-head GEMM + restore + BN stats --
// R3-exact structure: 64 nodes, 256 threads, 61504 B dyn smem.
// Only change: float2 weight loads in the head GEMM.
#define SM_XS   0          // [3*32][68]   xr rows i-1,i,i+1          6528 floats
#define SM_AL   6528       // [4*5][68]    alphas (0.25/den folded)   1360
#define SM_WH   7888       // [32][34]     W_h^T staging              1088
#define SM_Z    8976       // [32][68]     z_h / later nf             2176
#define SM_WR   11152      // [32][68]     w_restore^T                2176
#define SM_RED  13328      // 64*16 float2                            2048
#define SM_TOT  15376      // floats -> 61504 bytes

__global__ __launch_bounds__(256) void k_fused(
    const float* __restrict__ x,
    const float* __restrict__ w_lin,
    const float* __restrict__ w_restore,
    const float* __restrict__ b_gat)
{
    extern __shared__ float S[];
    float*  xs  = S + SM_XS;
    float*  al  = S + SM_AL;
    float*  Whs = S + SM_WH;
    float*  z   = S + SM_Z;
    float*  wrs = S + SM_WR;
    float2* red = (float2*)(S + SM_RED);

    const int t   = threadIdx.x;
    const int b   = blockIdx.x >> 8;
    const int rem = blockIdx.x & 255;
    const int i   = rem >> 1;
    const int j0  = (rem & 1) << 6;
    const size_t attB = (size_t)b * 8 * NN;

    // load w_restore^T [k][co]
    #pragma unroll
    for (int it = 0; it < 8; it++) {
        int idx = t + it * 256;
        int co = idx >> 5, k = idx & 31;
        wrs[k * 68 + co] = w_restore[idx];
    }
    // load xr halo: 3 rows x 32 cr x 66 cols (clamped)
    for (int idx = t; idx < 96 * 66; idx += 256) {
        int seg = idx / 66, slot = idx - seg * 66;
        int row3 = seg >> 5, cr = seg & 31;
        int srow = i - 1 + row3; srow = srow < 0 ? 0 : (srow > 127 ? 127 : srow);
        int col  = j0 - 1 + slot; col = col < 0 ? 0 : (col > 127 ? 127 : col);
        xs[seg * 68 + slot] = g_xr[((size_t)(b * CR + cr)) * NN + srow * 128 + col];
    }
    // alphas: thread = (h = t>>6, n = t&63)
    {
        const int h = t >> 6, n = t & 63;
        const int j = j0 + n;
        const int pos = i * 128 + j;
        const float* ps = &g_att[attB + (size_t)h * NN];
        const float* pd = &g_att[attB + (size_t)(4 + h) * NN];
        const float ad = pd[pos];
        const bool vu = (i > 0), vd = (i < HH - 1), vl = (j > 0), vr = (j < WW - 1);
        float e[5];
        float v;
        v = ps[pos] + ad;                       e[0] = v > 0.f ? v : 0.2f * v;
        v = (vu ? ps[pos - 128] : 0.f) + ad;    e[1] = vu ? (v > 0.f ? v : 0.2f * v) : -1e30f;
        v = (vd ? ps[pos + 128] : 0.f) + ad;    e[2] = vd ? (v > 0.f ? v : 0.2f * v) : -1e30f;
        v = (vl ? ps[pos - 1]   : 0.f) + ad;    e[3] = vl ? (v > 0.f ? v : 0.2f * v) : -1e30f;
        v = (vr ? ps[pos + 1]   : 0.f) + ad;    e[4] = vr ? (v > 0.f ? v : 0.2f * v) : -1e30f;
        float mx = e[0];
        #pragma unroll
        for (int s = 1; s < 5; s++) mx = fmaxf(mx, e[s]);
        float den = 0.f;
        #pragma unroll
        for (int s = 0; s < 5; s++) { e[s] = __expf(e[s] - mx); den += e[s]; }
        float sc = 0.25f / den;                 // head-mean folded in
        #pragma unroll
        for (int s = 0; s < 5; s++) al[(h * 5 + s) * 68 + n] = e[s] * sc;
    }
    __syncthreads();

    // per-head: z_h = sum_s alpha * xr[u_s];  nf += W_h @ z_h
    float acc[2][4];
    #pragma unroll
    for (int r = 0; r < 2; r++)
        #pragma unroll
        for (int c = 0; c < 4; c++) acc[r][c] = 0.f;

    const int co0g = (t & 15) * 2;      // gemm out-channel pair (even)
    const int n0g  = (t >> 4) * 4;      // gemm node quad
    const int nz   = t & 63;            // z-build node
    const int cr8  = (t >> 6) * 8;      // z-build cr block

    for (int h = 0; h < 4; h++) {
        #pragma unroll
        for (int it = 0; it < 4; it++) {
            int idx = t + it * 256;
            int co = idx >> 5, k = idx & 31;
            Whs[k * 34 + co] = w_lin[(h * CR + co) * CR + k];
        }
        __syncthreads();

        {
            const float a0 = al[(h * 5 + 0) * 68 + nz];
            const float a1 = al[(h * 5 + 1) * 68 + nz];
            const float a2 = al[(h * 5 + 2) * 68 + nz];
            const float a3 = al[(h * 5 + 3) * 68 + nz];
            const float a4 = al[(h * 5 + 4) * 68 + nz];
            #pragma unroll
            for (int cc = 0; cc < 8; cc++) {
                int cr = cr8 + cc;
                float vv = a0 * xs[(32 + cr) * 68 + nz + 1]
                         + a1 * xs[(     cr) * 68 + nz + 1]
                         + a2 * xs[(64 + cr) * 68 + nz + 1]
                         + a3 * xs[(32 + cr) * 68 + nz]
                         + a4 * xs[(32 + cr) * 68 + nz + 2];
                z[cr * 68 + nz] = vv;
            }
        }
        __syncthreads();

        #pragma unroll
        for (int k = 0; k < CR; k++) {
            float2 w2 = *(const float2*)&Whs[k * 34 + co0g];   // LDS.64 (co0g even)
            float4 zv = *(const float4*)&z[k * 68 + n0g];
            acc[0][0] += w2.x * zv.x; acc[0][1] += w2.x * zv.y; acc[0][2] += w2.x * zv.z; acc[0][3] += w2.x * zv.w;
            acc[1][0] += w2.y * zv.x; acc[1][1] += w2.y * zv.y; acc[1][2] += w2.y * zv.z; acc[1][3] += w2.y * zv.w;
        }
        __syncthreads();
    }

    // nf (+bias) -> z buffer
    #pragma unroll
    for (int r = 0; r < 2; r++) {
        float bg = b_gat[co0g + r];
        float4 v = make_float4(acc[r][0] + bg, acc[r][1] + bg, acc[r][2] + bg, acc[r][3] + bg);
        *(float4*)&z[(co0g + r) * 68 + n0g] = v;
    }
    __syncthreads();

    // restore GEMM + residual + stats: thread = 4 co x 4 n
    const int co0 = (t & 15) * 4;
    const int tn  = t >> 4;
    const int n0  = tn * 4;
    float a2[4][4];
    #pragma unroll
    for (int r = 0; r < 4; r++)
        #pragma unroll
        for (int c = 0; c < 4; c++) a2[r][c] = 0.f;

    #pragma unroll
    for (int k = 0; k < CR; k++) {
        float4 wv = *(const float4*)&wrs[k * 68 + co0];
        float4 xv = *(const float4*)&z[k * 68 + n0];
        a2[0][0] += wv.x * xv.x; a2[0][1] += wv.x * xv.y; a2[0][2] += wv.x * xv.z; a2[0][3] += wv.x * xv.w;
        a2[1][0] += wv.y * xv.x; a2[1][1] += wv.y * xv.y; a2[1][2] += wv.y * xv.z; a2[1][3] += wv.y * xv.w;
        a2[2][0] += wv.z * xv.x; a2[2][1] += wv.z * xv.y; a2[2][2] += wv.z * xv.z; a2[2][3] += wv.z * xv.w;
        a2[3][0] += wv.w * xv.x; a2[3][1] += wv.w * xv.y; a2[3][2] += wv.w * xv.z; a2[3][3] += wv.w * xv.w;
    }

    #pragma unroll
    for (int r = 0; r < 4; r++) {
        size_t base = ((size_t)(b * COUT + co0 + r)) * NN + i * 128 + j0 + n0;
        float4 rv = *(const float4*)&x[base];
        float4 v  = make_float4(a2[r][0] + rv.x, a2[r][1] + rv.y,
                                a2[r][2] + rv.z, a2[r][3] + rv.w);
        *(float4*)&g_pre[base] = v;
        float s = v.x + v.y + v.z + v.w;
        float q = v.x * v.x + v.y * v.y + v.z * v.z + v.w * v.w;
        red[(co0 + r) * 16 + tn] = make_float2(s, q);
    }
    __syncthreads();

    if (t < COUT) {
        float s = 0.f, q = 0.f;
        #pragma unroll
        for (int jj = 0; jj < 16; jj++) {
            float2 v = red[t * 16 + jj];
            s += v.x; q += v.y;
        }
        atomicAdd(&g_sum[t],   s);
        atomicAdd(&g_sumsq[t], q);
    }
}

// ---------------- kernel 3: BN finalize (inline) + normalize + relu --------
__global__ __launch_bounds__(256) void k_bnrelu(
    float* __restrict__ out,
    const float* __restrict__ gamma,
    const float* __restrict__ beta)
{
    __shared__ float s_scale[COUT], s_shift[COUT];
    const int t = threadIdx.x;
    if (t < COUT) {
        float inv_cnt = 1.f / (float)CNT;
        float mean = g_sum[t] * inv_cnt;
        float var  = g_sumsq[t] * inv_cnt - mean * mean;
        float sc   = gamma[t] / sqrtf(var + 1e-5f);
        s_scale[t] = sc;
        s_shift[t] = beta[t] - mean * sc;
    }
    __syncthreads();

    int idx = blockIdx.x * blockDim.x + t;             // float4 index
    int c = (idx >> 12) & 63;
    float sc = s_scale[c], sh = s_shift[c];
    float4 v = *(const float4*)&g_pre[(size_t)idx * 4];
    v.x = fmaxf(0.f, v.x * sc + sh);
    v.y = fmaxf(0.f, v.y * sc + sh);
    v.z = fmaxf(0.f, v.z * sc + sh);
    v.w = fmaxf(0.f, v.w * sc + sh);
    *(float4*)&out[(size_t)idx * 4] = v;
}

// ---------------- launch -----------------------------------------------------
extern "C" void kernel_launch(void* const* d_in, const int* in_sizes, int n_in,
                              void* d_out, int out_size)
{
    const float* x         = (const float*)d_in[0];
    const float* w_reduce  = (const float*)d_in[1];
    const float* w_lin     = (const float*)d_in[2];
    const float* att_src   = (const float*)d_in[3];
    const float* att_dst   = (const float*)d_in[4];
    const float* b_gat     = (const float*)d_in[5];
    const float* w_restore = (const float*)d_in[6];
    const float* bn_gamma  = (const float*)d_in[7];
    const float* bn_beta   = (const float*)d_in[8];
    // d_in[9]=src, d_in[10]=dst: structured 4-neighbor grid, recomputed analytically.

    cudaFuncSetAttribute(k_xr, cudaFuncAttributeMaxDynamicSharedMemorySize,
                         X_TOT * (int)sizeof(float));
    cudaFuncSetAttribute(k_fused, cudaFuncAttributeMaxDynamicSharedMemorySize,
                         SM_TOT * (int)sizeof(float));

    k_xr<<<BB * NN / 256, 256, X_TOT * sizeof(float)>>>(x, w_reduce, w_lin, att_src, att_dst);
    k_fused<<<BB * NN / 64, 256, SM_TOT * sizeof(float)>>>(x, w_lin, w_restore, b_gat);
    k_bnrelu<<<(BB * COUT * NN / 4) / 256, 256>>>((float*)d_out, bn_gamma, bn_beta);
}

// round 16
// speedup vs baseline: 1.0106x; 1.0106x over previous
#include <cuda_runtime.h>
#include <math.h>

#define BB    8
#define CIN   64
#define CR    32
#define HH    128
#define WW    128
#define NN    16384
#define COUT  64
#define CNT   (BB * NN)

// ---------------- device scratch ----------------
__device__ float g_xr[(size_t)BB * CR * NN];         // reduced features [b][cr][N]  16 MB
__device__ float g_att[(size_t)BB * 8 * NN];         // [b][rq][N]: rq 0-3 a_src, 4-7 a_dst
__device__ float g_pre[(size_t)BB * COUT * NN];      // pre-BN 33.5 MB
__device__ float g_sum[COUT];
__device__ float g_sumsq[COUT];

// ---------------- kernel 1: xr = w_reduce @ x (split-K) + attention rows ----
// 256 nodes / block, 256 threads. smem 43520 B -> 4 blocks/SM (reg-capped).
#define X_XS    0                      // 8320 floats: x half-tile [32][256] / xr [32][260]
#define X_WR    8320                   // [64][36] w_reduce^T (2304)
#define X_QS    10624                  // [32][8]  q^T (256)
#define X_TOT   10880                  // floats -> 43520 bytes

__global__ __launch_bounds__(256) void k_xr(
    const float* __restrict__ x,
    const float* __restrict__ w_reduce,
    const float* __restrict__ w_lin,
    const float* __restrict__ att_src,
    const float* __restrict__ att_dst)
{
    extern __shared__ float SX[];
    float* xs   = SX + X_XS;
    float* wr_s = SX + X_WR;
    float* qs   = SX + X_QS;

    const int t = threadIdx.x;
    const int b = blockIdx.x >> 6;
    const int nodeBase = (blockIdx.x & 63) << 8;

    if (blockIdx.x == 0 && t < COUT) { g_sum[t] = 0.f; g_sumsq[t] = 0.f; }

    #pragma unroll
    for (int i = 0; i < 8; i++) {
        int idx = t + i * 256;
        int cr = idx >> 6, c = idx & 63;
        wr_s[c * 36 + cr] = w_reduce[idx];
    }
    // q[rq][k] = sum_c att[h][c] * w_lin[h*32+c][k]  (attention linear in xr)
    {
        int rq = t >> 5, k = t & 31, h = rq & 3;
        const float* av = (rq < 4) ? att_src : att_dst;
        float acc = 0.f;
        #pragma unroll
        for (int c = 0; c < CR; c++)
            acc += av[h * CR + c] * w_lin[(h * CR + c) * CR + k];
        qs[k * 8 + rq] = acc;
    }

    const int crq = t & 7;
    const int cr0 = crq << 2;
    const int n0  = (t >> 3) << 3;
    float a1[4][8];
    #pragma unroll
    for (int i = 0; i < 4; i++)
        #pragma unroll
        for (int j = 0; j < 8; j++) a1[i][j] = 0.f;

    // split-K: two 32-channel halves through a [32][256] staging tile
    const float4* xg = (const float4*)x;
    float4* xs4 = (float4*)xs;
    for (int kt = 0; kt < 2; kt++) {
        #pragma unroll
        for (int i = 0; i < 8; i++) {
            int idx = t + i * 256;            // float4 index: c*64 + nq, c in 0..31
            int c = idx >> 6, nq = idx & 63;
            xs4[idx] = xg[((size_t)(b * CIN + kt * 32 + c)) * (NN / 4) + (nodeBase >> 2) + nq];
        }
        __syncthreads();

        #pragma unroll
        for (int c = 0; c < 32; c++) {
            float4 wv = *(const float4*)&wr_s[(kt * 32 + c) * 36 + cr0];
            float4 xa = *(const float4*)&xs[c * 256 + n0];
            float4 xb = *(const float4*)&xs[c * 256 + n0 + 4];
            a1[0][0] += wv.x * xa.x; a1[0][1] += wv.x * xa.y; a1[0][2] += wv.x * xa.z; a1[0][3] += wv.x * xa.w;
            a1[0][4] += wv.x * xb.x; a1[0][5] += wv.x * xb.y; a1[0][6] += wv.x * xb.z; a1[0][7] += wv.x * xb.w;
            a1[1][0] += wv.y * xa.x; a1[1][1] += wv.y * xa.y; a1[1][2] += wv.y * xa.z; a1[1][3] += wv.y * xa.w;
            a1[1][4] += wv.y * xb.x; a1[1][5] += wv.y * xb.y; a1[1][6] += wv.y * xb.z; a1[1][7] += wv.y * xb.w;
            a1[2][0] += wv.z * xa.x; a1[2][1] += wv.z * xa.y; a1[2][2] += wv.z * xa.z; a1[2][3] += wv.z * xa.w;
            a1[2][4] += wv.z * xb.x; a1[2][5] += wv.z * xb.y; a1[2][6] += wv.z * xb.z; a1[2][7] += wv.z * xb.w;
            a1[3][0] += wv.w * xa.x; a1[3][1] += wv.w * xa.y; a1[3][2] += wv.w * xa.z; a1[3][3] += wv.w * xa.w;
            a1[3][4] += wv.w * xb.x; a1[3][5] += wv.w * xb.y; a1[3][6] += wv.w * xb.z; a1[3][7] += wv.w * xb.w;
        }
        __syncthreads();                       // before next half overwrites xs
    }

    // write xr to global (coalesced float4 pairs)
    #pragma unroll
    for (int i = 0; i < 4; i++) {
        float4 va = make_float4(a1[i][0], a1[i][1], a1[i][2], a1[i][3]);
        float4 vb = make_float4(a1[i][4], a1[i][5], a1[i][6], a1[i][7]);
        size_t base = ((size_t)(b * CR + cr0 + i)) * NN + nodeBase + n0;
        *(float4*)&g_xr[base]     = va;
        *(float4*)&g_xr[base + 4] = vb;
    }
    // stash xr in smem [32][260] for the attention rows
    float* xrs = xs;
    #pragma unroll
    for (int i = 0; i < 4; i++) {
        float4 va = make_float4(a1[i][0], a1[i][1], a1[i][2], a1[i][3]);
        float4 vb = make_float4(a1[i][4], a1[i][5], a1[i][6], a1[i][7]);
        *(float4*)&xrs[(cr0 + i) * 260 + n0]     = va;
        *(float4*)&xrs[(cr0 + i) * 260 + n0 + 4] = vb;
    }
    __syncthreads();

    // attention rows: warp rq (0..7), lane handles 8 nodes
    const int rq   = t >> 5;
    const int lane = t & 31;
    const int na   = lane << 3;
    float p[8];
    #pragma unroll
    for (int i = 0; i < 8; i++) p[i] = 0.f;
    #pragma unroll
    for (int k = 0; k < CR; k++) {
        float qv = qs[k * 8 + rq];
        float4 xa = *(const float4*)&xrs[k * 260 + na];
        float4 xb = *(const float4*)&xrs[k * 260 + na + 4];
        p[0] += qv * xa.x; p[1] += qv * xa.y; p[2] += qv * xa.z; p[3] += qv * xa.w;
        p[4] += qv * xb.x; p[5] += qv * xb.y; p[6] += qv * xb.z; p[7] += qv * xb.w;
    }
    {
        size_t base = ((size_t)(b * 8 + rq)) * NN + nodeBase + na;
        *(float4*)&g_att[base]     = make_float4(p[0], p[1], p[2], p[3]);
        *(float4*)&g_att[base + 4] = make_float4(p[4], p[5], p[6], p[7]);
    }
}

// ---------------- kernel 2: fused agg + per-head GEMM + restore + BN stats --
// R3 structure; red overlays xs halo (dead after last z-build) -> 53312 B, 4 blocks/SM.
#define SM_XS   0          // [3*32][68]   xr rows i-1,i,i+1          6528 floats
#define SM_AL   6528       // [4*5][68]    alphas (0.25/den folded)   1360
#define SM_WH   7888       // [32][34]     W_h^T staging              1088
#define SM_Z    8976       // [32][68]     z_h / later nf             2176
#define SM_WR   11152      // [32][68]     w_restore^T                2176
#define SM_TOT  13328      // floats -> 53312 bytes
#define SM_RED  0          // 64*16 float2 overlays xs (dead in restore phase)

__global__ __launch_bounds__(256) void k_fused(
    const float* __restrict__ x,
    const float* __restrict__ w_lin,
    const float* __restrict__ w_restore,
    const float* __restrict__ b_gat)
{
    extern __shared__ float S[];
    float*  xs  = S + SM_XS;
    float*  al  = S + SM_AL;
    float*  Whs = S + SM_WH;
    float*  z   = S + SM_Z;
    float*  wrs = S + SM_WR;
    float2* red = (float2*)(S + SM_RED);

    const int t   = threadIdx.x;
    const int b   = blockIdx.x >> 8;
    const int rem = blockIdx.x & 255;
    const int i   = rem >> 1;
    const int j0  = (rem & 1) << 6;
    const size_t attB = (size_t)b * 8 * NN;

    // load w_restore^T [k][co]
    #pragma unroll
    for (int it = 0; it < 8; it++) {
        int idx = t + it * 256;
        int co = idx >> 5, k = idx & 31;
        wrs[k * 68 + co] = w_restore[idx];
    }
    // load xr halo: 3 rows x 32 cr x 66 cols (clamped)
    for (int idx = t; idx < 96 * 66; idx += 256) {
        int seg = idx / 66, slot = idx - seg * 66;
        int row3 = seg >> 5, cr = seg & 31;
        int srow = i - 1 + row3; srow = srow < 0 ? 0 : (srow > 127 ? 127 : srow);
        int col  = j0 - 1 + slot; col = col < 0 ? 0 : (col > 127 ? 127 : col);
        xs[seg * 68 + slot] = g_xr[((size_t)(b * CR + cr)) * NN + srow * 128 + col];
    }
    // alphas: thread = (h = t>>6, n = t&63)
    {
        const int h = t >> 6, n = t & 63;
        const int j = j0 + n;
        const int pos = i * 128 + j;
        const float* ps = &g_att[attB + (size_t)h * NN];
        const float* pd = &g_att[attB + (size_t)(4 + h) * NN];
        const float ad = pd[pos];
        const bool vu = (i > 0), vd = (i < HH - 1), vl = (j > 0), vr = (j < WW - 1);
        float e[5];
        float v;
        v = ps[pos] + ad;                       e[0] = v > 0.f ? v : 0.2f * v;
        v = (vu ? ps[pos - 128] : 0.f) + ad;    e[1] = vu ? (v > 0.f ? v : 0.2f * v) : -1e30f;
        v = (vd ? ps[pos + 128] : 0.f) + ad;    e[2] = vd ? (v > 0.f ? v : 0.2f * v) : -1e30f;
        v = (vl ? ps[pos - 1]   : 0.f) + ad;    e[3] = vl ? (v > 0.f ? v : 0.2f * v) : -1e30f;
        v = (vr ? ps[pos + 1]   : 0.f) + ad;    e[4] = vr ? (v > 0.f ? v : 0.2f * v) : -1e30f;
        float mx = e[0];
        #pragma unroll
        for (int s = 1; s < 5; s++) mx = fmaxf(mx, e[s]);
        float den = 0.f;
        #pragma unroll
        for (int s = 0; s < 5; s++) { e[s] = __expf(e[s] - mx); den += e[s]; }
        float sc = 0.25f / den;                 // head-mean folded in
        #pragma unroll
        for (int s = 0; s < 5; s++) al[(h * 5 + s) * 68 + n] = e[s] * sc;
    }
    __syncthreads();

    // per-head: z_h = sum_s alpha * xr[u_s];  nf += W_h @ z_h
    float acc[2][4];
    #pragma unroll
    for (int r = 0; r < 2; r++)
        #pragma unroll
        for (int c = 0; c < 4; c++) acc[r][c] = 0.f;

    const int co0g = (t & 15) * 2;      // gemm out-channel pair (even)
    const int n0g  = (t >> 4) * 4;      // gemm node quad
    const int nz   = t & 63;            // z-build node
    const int cr8  = (t >> 6) * 8;      // z-build cr block

    for (int h = 0; h < 4; h++) {
        #pragma unroll
        for (int it = 0; it < 4; it++) {
            int idx = t + it * 256;
            int co = idx >> 5, k = idx & 31;
            Whs[k * 34 + co] = w_lin[(h * CR + co) * CR + k];
        }
        __syncthreads();

        {
            const float a0 = al[(h * 5 + 0) * 68 + nz];
            const float a1 = al[(h * 5 + 1) * 68 + nz];
            const float a2 = al[(h * 5 + 2) * 68 + nz];
            const float a3 = al[(h * 5 + 3) * 68 + nz];
            const float a4 = al[(h * 5 + 4) * 68 + nz];
            #pragma unroll
            for (int cc = 0; cc < 8; cc++) {
                int cr = cr8 + cc;
                float vv = a0 * xs[(32 + cr) * 68 + nz + 1]
                         + a1 * xs[(     cr) * 68 + nz + 1]
                         + a2 * xs[(64 + cr) * 68 + nz + 1]
                         + a3 * xs[(32 + cr) * 68 + nz]
                         + a4 * xs[(32 + cr) * 68 + nz + 2];
                z[cr * 68 + nz] = vv;
            }
        }
        __syncthreads();

        #pragma unroll
        for (int k = 0; k < CR; k++) {
            float2 w2 = *(const float2*)&Whs[k * 34 + co0g];   // LDS.64
            float4 zv = *(const float4*)&z[k * 68 + n0g];
            acc[0][0] += w2.x * zv.x; acc[0][1] += w2.x * zv.y; acc[0][2] += w2.x * zv.z; acc[0][3] += w2.x * zv.w;
            acc[1][0] += w2.y * zv.x; acc[1][1] += w2.y * zv.y; acc[1][2] += w2.y * zv.z; acc[1][3] += w2.y * zv.w;
        }
        __syncthreads();
    }

    // nf (+bias) -> z buffer
    #pragma unroll
    for (int r = 0; r < 2; r++) {
        float bg = b_gat[co0g + r];
        float4 v = make_float4(acc[r][0] + bg, acc[r][1] + bg, acc[r][2] + bg, acc[r][3] + bg);
        *(float4*)&z[(co0g + r) * 68 + n0g] = v;
    }
    __syncthreads();

    // restore GEMM + residual + stats: thread = 4 co x 4 n
    const int co0 = (t & 15) * 4;
    const int tn  = t >> 4;
    const int n0  = tn * 4;
    float a2[4][4];
    #pragma unroll
    for (int r = 0; r < 4; r++)
        #pragma unroll
        for (int c = 0; c < 4; c++) a2[r][c] = 0.f;

    #pragma unroll
    for (int k = 0; k < CR; k++) {
        float4 wv = *(const float4*)&wrs[k * 68 + co0];
        float4 xv = *(const float4*)&z[k * 68 + n0];
        a2[0][0] += wv.x * xv.x; a2[0][1] += wv.x * xv.y; a2[0][2] += wv.x * xv.z; a2[0][3] += wv.x * xv.w;
        a2[1][0] += wv.y * xv.x; a2[1][1] += wv.y * xv.y; a2[1][2] += wv.y * xv.z; a2[1][3] += wv.y * xv.w;
        a2[2][0] += wv.z * xv.x; a2[2][1] += wv.z * xv.y; a2[2][2] += wv.z * xv.z; a2[2][3] += wv.z * xv.w;
        a2[3][0] += wv.w * xv.x; a2[3][1] += wv.w * xv.y; a2[3][2] += wv.w * xv.z; a2[3][3] += wv.w * xv.w;
    }

    #pragma unroll
    for (int r = 0; r < 4; r++) {
        size_t base = ((size_t)(b * COUT + co0 + r)) * NN + i * 128 + j0 + n0;
        float4 rv = *(const float4*)&x[base];
        float4 v  = make_float4(a2[r][0] + rv.x, a2[r][1] + rv.y,
                                a2[r][2] + rv.z, a2[r][3] + rv.w);
        *(float4*)&g_pre[base] = v;
        float s = v.x + v.y + v.z + v.w;
        float q = v.x * v.x + v.y * v.y + v.z * v.z + v.w * v.w;
        red[(co0 + r) * 16 + tn] = make_float2(s, q);   // xs region (dead)
    }
    __syncthreads();

    if (t < COUT) {
        float s = 0.f, q = 0.f;
        #pragma unroll
        for (int jj = 0; jj < 16; jj++) {
            float2 v = red[t * 16 + jj];
            s += v.x; q += v.y;
        }
        atomicAdd(&g_sum[t],   s);
        atomicAdd(&g_sumsq[t], q);
    }
}

// ---------------- kernel 3: BN finalize (inline) + normalize + relu --------
__global__ __launch_bounds__(256) void k_bnrelu(
    float* __restrict__ out,
    const float* __restrict__ gamma,
    const float* __restrict__ beta)
{
    __shared__ float s_scale[COUT], s_shift[COUT];
    const int t = threadIdx.x;
    if (t < COUT) {
        float inv_cnt = 1.f / (float)CNT;
        float mean = g_sum[t] * inv_cnt;
        float var  = g_sumsq[t] * inv_cnt - mean * mean;
        float sc   = gamma[t] / sqrtf(var + 1e-5f);
        s_scale[t] = sc;
        s_shift[t] = beta[t] - mean * sc;
    }
    __syncthreads();

    int idx = blockIdx.x * blockDim.x + t;             // float4 index
    int c = (idx >> 12) & 63;
    float sc = s_scale[c], sh = s_shift[c];
    float4 v = *(const float4*)&g_pre[(size_t)idx * 4];
    v.x = fmaxf(0.f, v.x * sc + sh);
    v.y = fmaxf(0.f, v.y * sc + sh);
    v.z = fmaxf(0.f, v.z * sc + sh);
    v.w = fmaxf(0.f, v.w * sc + sh);
    *(float4*)&out[(size_t)idx * 4] = v;
}

// ---------------- launch -----------------------------------------------------
extern "C" void kernel_launch(void* const* d_in, const int* in_sizes, int n_in,
                              void* d_out, int out_size)
{
    const float* x         = (const float*)d_in[0];
    const float* w_reduce  = (const float*)d_in[1];
    const float* w_lin     = (const float*)d_in[2];
    const float* att_src   = (const float*)d_in[3];
    const float* att_dst   = (const float*)d_in[4];
    const float* b_gat     = (const float*)d_in[5];
    const float* w_restore = (const float*)d_in[6];
    const float* bn_gamma  = (const float*)d_in[7];
    const float* bn_beta   = (const float*)d_in[8];
    // d_in[9]=src, d_in[10]=dst: structured 4-neighbor grid, recomputed analytically.

    cudaFuncSetAttribute(k_xr, cudaFuncAttributeMaxDynamicSharedMemorySize,
                         X_TOT * (int)sizeof(float));
    cudaFuncSetAttribute(k_fused, cudaFuncAttributeMaxDynamicSharedMemorySize,
                         SM_TOT * (int)sizeof(float));

    k_xr<<<BB * NN / 256, 256, X_TOT * sizeof(float)>>>(x, w_reduce, w_lin, att_src, att_dst);
    k_fused<<<BB * NN / 64, 256, SM_TOT * sizeof(float)>>>(x, w_lin, w_restore, b_gat);
    k_bnrelu<<<(BB * COUT * NN / 4) / 256, 256>>>((float*)d_out, bn_gamma, bn_beta);
}

// round 17
// speedup vs baseline: 1.0544x; 1.0433x over previous
#include <cuda_runtime.h>
#include <math.h>

#define BB    8
#define CIN   64
#define CR    32
#define HH    128
#define WW    128
#define NN    16384
#define COUT  64
#define CNT   (BB * NN)

// ---------------- device scratch ----------------
__device__ float g_xr[(size_t)BB * CR * NN];         // reduced features [b][cr][N]  16 MB
__device__ float g_att[(size_t)BB * 8 * NN];         // [b][rq][N]: rq 0-3 a_src, 4-7 a_dst
__device__ float g_pre[(size_t)BB * COUT * NN];      // pre-BN 33.5 MB
__device__ float g_sum[COUT];
__device__ float g_sumsq[COUT];

// ---------------- kernel 1: xr = w_reduce @ x (split-K) + attention rows ----
// 256 nodes / block, 512 threads, 4cr x 4n microtile (low reg pressure).
// smem 43520 B. __launch_bounds__(512,2) guarantees >=32 warps/SM.
#define X_XS    0                      // 8320 floats: x half-tile [32][256] / xr [32][260]
#define X_WR    8320                   // [64][36] w_reduce^T (2304)
#define X_QS    10624                  // [32][8]  q^T (256)
#define X_TOT   10880                  // floats -> 43520 bytes

__global__ __launch_bounds__(512, 2) void k_xr(
    const float* __restrict__ x,
    const float* __restrict__ w_reduce,
    const float* __restrict__ w_lin,
    const float* __restrict__ att_src,
    const float* __restrict__ att_dst)
{
    extern __shared__ float SX[];
    float* xs   = SX + X_XS;
    float* wr_s = SX + X_WR;
    float* qs   = SX + X_QS;

    const int t = threadIdx.x;
    const int b = blockIdx.x >> 6;
    const int nodeBase = (blockIdx.x & 63) << 8;

    if (blockIdx.x == 0 && t < COUT) { g_sum[t] = 0.f; g_sumsq[t] = 0.f; }

    // w_reduce^T -> wr_s[c][cr]
    #pragma unroll
    for (int i = 0; i < 4; i++) {
        int idx = t + i * 512;
        int cr = idx >> 6, c = idx & 63;
        wr_s[c * 36 + cr] = w_reduce[idx];
    }
    // q[rq][k] = sum_c att[h][c] * w_lin[h*32+c][k]  (attention linear in xr)
    if (t < 256) {
        int rq = t >> 5, k = t & 31, h = rq & 3;
        const float* av = (rq < 4) ? att_src : att_dst;
        float acc = 0.f;
        #pragma unroll
        for (int c = 0; c < CR; c++)
            acc += av[h * CR + c] * w_lin[(h * CR + c) * CR + k];
        qs[k * 8 + rq] = acc;
    }

    const int crq = t >> 6;          // 0..7  (warp-uniform)
    const int cr0 = crq << 2;
    const int nd  = t & 63;
    const int n0  = nd << 2;
    float a1[4][4];
    #pragma unroll
    for (int i = 0; i < 4; i++)
        #pragma unroll
        for (int j = 0; j < 4; j++) a1[i][j] = 0.f;

    // split-K: two 32-channel halves through a [32][256] staging tile
    const float4* xg = (const float4*)x;
    float4* xs4 = (float4*)xs;
    for (int kt = 0; kt < 2; kt++) {
        #pragma unroll
        for (int i = 0; i < 4; i++) {
            int idx = t + i * 512;            // float4 index: c*64 + nq, c in 0..31
            int c = idx >> 6, nq = idx & 63;
            xs4[idx] = xg[((size_t)(b * CIN + kt * 32 + c)) * (NN / 4) + (nodeBase >> 2) + nq];
        }
        __syncthreads();

        #pragma unroll
        for (int c = 0; c < 32; c++) {
            float4 wv = *(const float4*)&wr_s[(kt * 32 + c) * 36 + cr0];  // warp-broadcast
            float4 xv = *(const float4*)&xs[c * 256 + n0];                // 512B span, conflict-free
            a1[0][0] += wv.x * xv.x; a1[0][1] += wv.x * xv.y; a1[0][2] += wv.x * xv.z; a1[0][3] += wv.x * xv.w;
            a1[1][0] += wv.y * xv.x; a1[1][1] += wv.y * xv.y; a1[1][2] += wv.y * xv.z; a1[1][3] += wv.y * xv.w;
            a1[2][0] += wv.z * xv.x; a1[2][1] += wv.z * xv.y; a1[2][2] += wv.z * xv.z; a1[2][3] += wv.z * xv.w;
            a1[3][0] += wv.w * xv.x; a1[3][1] += wv.w * xv.y; a1[3][2] += wv.w * xv.z; a1[3][3] += wv.w * xv.w;
        }
        __syncthreads();                       // before next half overwrites xs
    }

    // write xr to global (per-warp: one plane, 512B fully coalesced)
    #pragma unroll
    for (int i = 0; i < 4; i++) {
        float4 v = make_float4(a1[i][0], a1[i][1], a1[i][2], a1[i][3]);
        *(float4*)&g_xr[((size_t)(b * CR + cr0 + i)) * NN + nodeBase + n0] = v;
    }
    // stash xr in smem [32][260] for the attention rows
    float* xrs = xs;
    #pragma unroll
    for (int i = 0; i < 4; i++) {
        float4 v = make_float4(a1[i][0], a1[i][1], a1[i][2], a1[i][3]);
        *(float4*)&xrs[(cr0 + i) * 260 + n0] = v;
    }
    __syncthreads();

    // attention rows: group rq = t>>6 (warp-uniform), thread handles 4 nodes
    {
        const int rq = crq;
        float p0 = 0.f, p1 = 0.f, p2 = 0.f, p3 = 0.f;
        #pragma unroll
        for (int k = 0; k < CR; k++) {
            float qv = qs[k * 8 + rq];                       // broadcast
            float4 xv = *(const float4*)&xrs[k * 260 + n0];  // 512B span
            p0 += qv * xv.x; p1 += qv * xv.y; p2 += qv * xv.z; p3 += qv * xv.w;
        }
        *(float4*)&g_att[((size_t)(b * 8 + rq)) * NN + nodeBase + n0] =
            make_float4(p0, p1, p2, p3);
    }
}

// ---------------- kernel 2: fused agg + per-head GEMM + restore + BN stats --
// R16-exact (measured 150.4 config): 64 nodes, 256 threads, 53312 B, red overlays xs.
#define SM_XS   0          // [3*32][68]   xr rows i-1,i,i+1          6528 floats
#define SM_AL   6528       // [4*5][68]    alphas (0.25/den folded)   1360
#define SM_WH   7888       // [32][34]     W_h^T staging              1088
#define SM_Z    8976       // [32][68]     z_h / later nf             2176
#define SM_WR   11152      // [32][68]     w_restore^T                2176
#define SM_TOT  13328      // floats -> 53312 bytes
#define SM_RED  0          // 64*16 float2 overlays xs (dead in restore phase)

__global__ __launch_bounds__(256) void k_fused(
    const float* __restrict__ x,
    const float* __restrict__ w_lin,
    const float* __restrict__ w_restore,
    const float* __restrict__ b_gat)
{
    extern __shared__ float S[];
    float*  xs  = S + SM_XS;
    float*  al  = S + SM_AL;
    float*  Whs = S + SM_WH;
    float*  z   = S + SM_Z;
    float*  wrs = S + SM_WR;
    float2* red = (float2*)(S + SM_RED);

    const int t   = threadIdx.x;
    const int b   = blockIdx.x >> 8;
    const int rem = blockIdx.x & 255;
    const int i   = rem >> 1;
    const int j0  = (rem & 1) << 6;
    const size_t attB = (size_t)b * 8 * NN;

    // load w_restore^T [k][co]
    #pragma unroll
    for (int it = 0; it < 8; it++) {
        int idx = t + it * 256;
        int co = idx >> 5, k = idx & 31;
        wrs[k * 68 + co] = w_restore[idx];
    }
    // load xr halo: 3 rows x 32 cr x 66 cols (clamped)
    for (int idx = t; idx < 96 * 66; idx += 256) {
        int seg = idx / 66, slot = idx - seg * 66;
        int row3 = seg >> 5, cr = seg & 31;
        int srow = i - 1 + row3; srow = srow < 0 ? 0 : (srow > 127 ? 127 : srow);
        int col  = j0 - 1 + slot; col = col < 0 ? 0 : (col > 127 ? 127 : col);
        xs[seg * 68 + slot] = g_xr[((size_t)(b * CR + cr)) * NN + srow * 128 + col];
    }
    // alphas: thread = (h = t>>6, n = t&63)
    {
        const int h = t >> 6, n = t & 63;
        const int j = j0 + n;
        const int pos = i * 128 + j;
        const float* ps = &g_att[attB + (size_t)h * NN];
        const float* pd = &g_att[attB + (size_t)(4 + h) * NN];
        const float ad = pd[pos];
        const bool vu = (i > 0), vd = (i < HH - 1), vl = (j > 0), vr = (j < WW - 1);
        float e[5];
        float v;
        v = ps[pos] + ad;                       e[0] = v > 0.f ? v : 0.2f * v;
        v = (vu ? ps[pos - 128] : 0.f) + ad;    e[1] = vu ? (v > 0.f ? v : 0.2f * v) : -1e30f;
        v = (vd ? ps[pos + 128] : 0.f) + ad;    e[2] = vd ? (v > 0.f ? v : 0.2f * v) : -1e30f;
        v = (vl ? ps[pos - 1]   : 0.f) + ad;    e[3] = vl ? (v > 0.f ? v : 0.2f * v) : -1e30f;
        v = (vr ? ps[pos + 1]   : 0.f) + ad;    e[4] = vr ? (v > 0.f ? v : 0.2f * v) : -1e30f;
        float mx = e[0];
        #pragma unroll
        for (int s = 1; s < 5; s++) mx = fmaxf(mx, e[s]);
        float den = 0.f;
        #pragma unroll
        for (int s = 0; s < 5; s++) { e[s] = __expf(e[s] - mx); den += e[s]; }
        float sc = 0.25f / den;                 // head-mean folded in
        #pragma unroll
        for (int s = 0; s < 5; s++) al[(h * 5 + s) * 68 + n] = e[s] * sc;
    }
    __syncthreads();

    // per-head: z_h = sum_s alpha * xr[u_s];  nf += W_h @ z_h
    float acc[2][4];
    #pragma unroll
    for (int r = 0; r < 2; r++)
        #pragma unroll
        for (int c = 0; c < 4; c++) acc[r][c] = 0.f;

    const int co0g = (t & 15) * 2;      // gemm out-channel pair (even)
    const int n0g  = (t >> 4) * 4;      // gemm node quad
    const int nz   = t & 63;            // z-build node
    const int cr8  = (t >> 6) * 8;      // z-build cr block

    for (int h = 0; h < 4; h++) {
        #pragma unroll
        for (int it = 0; it < 4; it++) {
            int idx = t + it * 256;
            int co = idx >> 5, k = idx & 31;
            Whs[k * 34 + co] = w_lin[(h * CR + co) * CR + k];
        }
        __syncthreads();

        {
            const float a0 = al[(h * 5 + 0) * 68 + nz];
            const float a1 = al[(h * 5 + 1) * 68 + nz];
            const float a2 = al[(h * 5 + 2) * 68 + nz];
            const float a3 = al[(h * 5 + 3) * 68 + nz];
            const float a4 = al[(h * 5 + 4) * 68 + nz];
            #pragma unroll
            for (int cc = 0; cc < 8; cc++) {
                int cr = cr8 + cc;
                float vv = a0 * xs[(32 + cr) * 68 + nz + 1]
                         + a1 * xs[(     cr) * 68 + nz + 1]
                         + a2 * xs[(64 + cr) * 68 + nz + 1]
                         + a3 * xs[(32 + cr) * 68 + nz]
                         + a4 * xs[(32 + cr) * 68 + nz + 2];
                z[cr * 68 + nz] = vv;
            }
        }
        __syncthreads();

        #pragma unroll
        for (int k = 0; k < CR; k++) {
            float2 w2 = *(const float2*)&Whs[k * 34 + co0g];   // LDS.64
            float4 zv = *(const float4*)&z[k * 68 + n0g];
            acc[0][0] += w2.x * zv.x; acc[0][1] += w2.x * zv.y; acc[0][2] += w2.x * zv.z; acc[0][3] += w2.x * zv.w;
            acc[1][0] += w2.y * zv.x; acc[1][1] += w2.y * zv.y; acc[1][2] += w2.y * zv.z; acc[1][3] += w2.y * zv.w;
        }
        __syncthreads();
    }

    // nf (+bias) -> z buffer
    #pragma unroll
    for (int r = 0; r < 2; r++) {
        float bg = b_gat[co0g + r];
        float4 v = make_float4(acc[r][0] + bg, acc[r][1] + bg, acc[r][2] + bg, acc[r][3] + bg);
        *(float4*)&z[(co0g + r) * 68 + n0g] = v;
    }
    __syncthreads();

    // restore GEMM + residual + stats: thread = 4 co x 4 n
    const int co0 = (t & 15) * 4;
    const int tn  = t >> 4;
    const int n0  = tn * 4;
    float a2[4][4];
    #pragma unroll
    for (int r = 0; r < 4; r++)
        #pragma unroll
        for (int c = 0; c < 4; c++) a2[r][c] = 0.f;

    #pragma unroll
    for (int k = 0; k < CR; k++) {
        float4 wv = *(const float4*)&wrs[k * 68 + co0];
        float4 xv = *(const float4*)&z[k * 68 + n0];
        a2[0][0] += wv.x * xv.x; a2[0][1] += wv.x * xv.y; a2[0][2] += wv.x * xv.z; a2[0][3] += wv.x * xv.w;
        a2[1][0] += wv.y * xv.x; a2[1][1] += wv.y * xv.y; a2[1][2] += wv.y * xv.z; a2[1][3] += wv.y * xv.w;
        a2[2][0] += wv.z * xv.x; a2[2][1] += wv.z * xv.y; a2[2][2] += wv.z * xv.z; a2[2][3] += wv.z * xv.w;
        a2[3][0] += wv.w * xv.x; a2[3][1] += wv.w * xv.y; a2[3][2] += wv.w * xv.z; a2[3][3] += wv.w * xv.w;
    }

    #pragma unroll
    for (int r = 0; r < 4; r++) {
        size_t base = ((size_t)(b * COUT + co0 + r)) * NN + i * 128 + j0 + n0;
        float4 rv = *(const float4*)&x[base];
        float4 v  = make_float4(a2[r][0] + rv.x, a2[r][1] + rv.y,
                                a2[r][2] + rv.z, a2[r][3] + rv.w);
        *(float4*)&g_pre[base] = v;
        float s = v.x + v.y + v.z + v.w;
        float q = v.x * v.x + v.y * v.y + v.z * v.z + v.w * v.w;
        red[(co0 + r) * 16 + tn] = make_float2(s, q);   // xs region (dead)
    }
    __syncthreads();

    if (t < COUT) {
        float s = 0.f, q = 0.f;
        #pragma unroll
        for (int jj = 0; jj < 16; jj++) {
            float2 v = red[t * 16 + jj];
            s += v.x; q += v.y;
        }
        atomicAdd(&g_sum[t],   s);
        atomicAdd(&g_sumsq[t], q);
    }
}

// ---------------- kernel 3: BN finalize (inline) + normalize + relu --------
__global__ __launch_bounds__(256) void k_bnrelu(
    float* __restrict__ out,
    const float* __restrict__ gamma,
    const float* __restrict__ beta)
{
    __shared__ float s_scale[COUT], s_shift[COUT];
    const int t = threadIdx.x;
    if (t < COUT) {
        float inv_cnt = 1.f / (float)CNT;
        float mean = g_sum[t] * inv_cnt;
        float var  = g_sumsq[t] * inv_cnt - mean * mean;
        float sc   = gamma[t] / sqrtf(var + 1e-5f);
        s_scale[t] = sc;
        s_shift[t] = beta[t] - mean * sc;
    }
    __syncthreads();

    int idx = blockIdx.x * blockDim.x + t;             // float4 index
    int c = (idx >> 12) & 63;
    float sc = s_scale[c], sh = s_shift[c];
    float4 v = *(const float4*)&g_pre[(size_t)idx * 4];
    v.x = fmaxf(0.f, v.x * sc + sh);
    v.y = fmaxf(0.f, v.y * sc + sh);
    v.z = fmaxf(0.f, v.z * sc + sh);
    v.w = fmaxf(0.f, v.w * sc + sh);
    *(float4*)&out[(size_t)idx * 4] = v;
}

// ---------------- launch -----------------------------------------------------
extern "C" void kernel_launch(void* const* d_in, const int* in_sizes, int n_in,
                              void* d_out, int out_size)
{
    const float* x         = (const float*)d_in[0];
    const float* w_reduce  = (const float*)d_in[1];
    const float* w_lin     = (const float*)d_in[2];
    const float* att_src   = (const float*)d_in[3];
    const float* att_dst   = (const float*)d_in[4];
    const float* b_gat     = (const float*)d_in[5];
    const float* w_restore = (const float*)d_in[6];
    const float* bn_gamma  = (const float*)d_in[7];
    const float* bn_beta   = (const float*)d_in[8];
    // d_in[9]=src, d_in[10]=dst: structured 4-neighbor grid, recomputed analytically.

    cudaFuncSetAttribute(k_xr, cudaFuncAttributeMaxDynamicSharedMemorySize,
                         X_TOT * (int)sizeof(float));
    cudaFuncSetAttribute(k_fused, cudaFuncAttributeMaxDynamicSharedMemorySize,
                         SM_TOT * (int)sizeof(float));

    k_xr<<<BB * NN / 256, 512, X_TOT * sizeof(float)>>>(x, w_reduce, w_lin, att_src, att_dst);
    k_fused<<<BB * NN / 64, 256, SM_TOT * sizeof(float)>>>(x, w_lin, w_restore, b_gat);
    k_bnrelu<<<(BB * COUT * NN / 4) / 256, 256>>>((float*)d_out, bn_gamma, bn_beta);
}